// round 9
// baseline (speedup 1.0000x reference)
#include <cuda_runtime.h>
#include <cuda_fp16.h>
#include <cstdint>

#define T_DIM 8192
#define K_DIM 4096
#define N_DIM 4096
#define R_DIM 64
#define NGRP  8

// ---------------- static device scratch (alloc forbidden) -------------------
__device__ __half g_x16[(size_t)T_DIM * K_DIM];
__device__ __half g_w16[(size_t)N_DIM * K_DIM];
__device__ __half g_la16[(size_t)NGRP * R_DIM * K_DIM];
__device__ __half g_lb16[(size_t)NGRP * N_DIM * R_DIM];   // [g][n][r] transposed
__device__ __half g_sh16[(size_t)T_DIM * R_DIM];

// ---------------- asm helpers (base ISA only: sm_80-class) ------------------
__device__ __forceinline__ uint32_t smem_u32(const void* p) {
    uint32_t a;
    asm("{ .reg .u64 t; cvta.to.shared.u64 t, %1; cvt.u32.u64 %0, t; }"
        : "=r"(a) : "l"(p));
    return a;
}
#define CP16(dst, src) \
    asm volatile("cp.async.cg.shared.global [%0], [%1], 16;" :: "r"(dst), "l"(src))
#define CP_COMMIT() asm volatile("cp.async.commit_group;" ::: "memory")
#define CP_WAIT2()  asm volatile("cp.async.wait_group 2;"  ::: "memory")

#define LDSM4(d, addr) \
    asm volatile("ldmatrix.sync.aligned.m8n8.x4.shared.b16 {%0,%1,%2,%3}, [%4];" \
        : "=r"((d)[0]), "=r"((d)[1]), "=r"((d)[2]), "=r"((d)[3]) : "r"(addr))

#define MMA_F16(ac, a, b0, b1) \
    asm volatile("mma.sync.aligned.m16n8k16.row.col.f32.f16.f16.f32 " \
        "{%0,%1,%2,%3}, {%4,%5,%6,%7}, {%8,%9}, {%0,%1,%2,%3};" \
        : "+f"((ac)[0]), "+f"((ac)[1]), "+f"((ac)[2]), "+f"((ac)[3]) \
        : "r"((a)[0]), "r"((a)[1]), "r"((a)[2]), "r"((a)[3]), "r"(b0), "r"(b1))

// smem byte offset of 16B chunk (row, ch) within a tile of 128B rows (BK=64).
// Full 8-way XOR swizzle: ldmatrix (8 rows, same ch) hits 8 distinct 16B banks.
__device__ __forceinline__ uint32_t swz(int row, int ch) {
    return (uint32_t)((row << 7) | (((ch ^ (row & 7)) & 7) << 4));
}

__device__ __forceinline__ int find_group(const int* __restrict__ gl,
                                          int n_groups, int token) {
    int g = 0;
    while (g < n_groups - 1 && token >= gl[g]) g++;
    return g;
}

// ---------------- pre-pass kernels ------------------------------------------
__global__ __launch_bounds__(256) void cvt_x_kernel(const float* __restrict__ in) {
    int i = blockIdx.x * 256 + threadIdx.x;
    float4 v = reinterpret_cast<const float4*>(in)[i];
    reinterpret_cast<__half2*>(g_x16)[2 * i]     = __floats2half2_rn(v.x, v.y);
    reinterpret_cast<__half2*>(g_x16)[2 * i + 1] = __floats2half2_rn(v.z, v.w);
}
__global__ __launch_bounds__(256) void cvt_w_kernel(const float* __restrict__ in) {
    int i = blockIdx.x * 256 + threadIdx.x;
    float4 v = reinterpret_cast<const float4*>(in)[i];
    reinterpret_cast<__half2*>(g_w16)[2 * i]     = __floats2half2_rn(v.x, v.y);
    reinterpret_cast<__half2*>(g_w16)[2 * i + 1] = __floats2half2_rn(v.z, v.w);
}
__global__ __launch_bounds__(256) void cvt_la_kernel(const float* __restrict__ in) {
    int i = blockIdx.x * 256 + threadIdx.x;
    float4 v = reinterpret_cast<const float4*>(in)[i];
    reinterpret_cast<__half2*>(g_la16)[2 * i]     = __floats2half2_rn(v.x, v.y);
    reinterpret_cast<__half2*>(g_la16)[2 * i + 1] = __floats2half2_rn(v.z, v.w);
}

// transpose lora_b[g][r][n] -> [g][n][r] fp16
__global__ __launch_bounds__(256) void lorab_t_kernel(const float* __restrict__ lb) {
    __shared__ float t[64][65];
    int g = blockIdx.y;
    int n0 = blockIdx.x * 64;
    for (int idx = threadIdx.x; idx < 4096; idx += 256) {
        int r = idx >> 6, n = idx & 63;
        t[n][r] = lb[((size_t)g * R_DIM + r) * N_DIM + n0 + n];
    }
    __syncthreads();
    for (int idx = threadIdx.x; idx < 4096; idx += 256) {
        int n = idx >> 6, r = idx & 63;
        g_lb16[((size_t)g * N_DIM + n0 + n) * R_DIM + r] = __float2half_rn(t[n][r]);
    }
}

// =============================================================================
// Shrink GEMM: shrink[8192,64] = x @ lora_a[g]^T, single fp16 term.
// CTA tile 128x64, 256 threads (8 warps: 4m x 2n, warp tile 32x32), BK=64.
// =============================================================================
#define SH_STAGE 24576
#define SH_CHUNKS (K_DIM / 64)   // 64

__global__ __launch_bounds__(256, 1) void shrink_gemm(
    const int* __restrict__ gl, int n_groups)
{
    extern __shared__ char smem[];
    uint32_t sb = smem_u32(smem);
    int tid = threadIdx.x, lane = tid & 31, w = tid >> 5;
    int m_off = (w & 3) * 32, n_off = (w >> 2) * 32;
    int row0 = blockIdx.x * 128;
    int g = find_group(gl, n_groups, row0);

    const __half* A = g_x16 + (size_t)row0 * K_DIM;
    const __half* B = g_la16 + (size_t)g * R_DIM * K_DIM;

    float acc[2][4][4];
    #pragma unroll
    for (int i = 0; i < 2; i++)
        #pragma unroll
        for (int j = 0; j < 4; j++)
            #pragma unroll
            for (int q = 0; q < 4; q++) acc[i][j][q] = 0.f;

    auto fill = [&](int s, int c) {
        uint32_t st = sb + s * SH_STAGE;
        #pragma unroll
        for (int it = 0; it < 6; it++) {
            int idx = tid + it * 256;
            if (idx < 1024) {               // A: 128 rows x 8 ch
                int row = idx >> 3, ch = idx & 7;
                CP16(st + swz(row, ch),
                     A + (size_t)row * K_DIM + c * 64 + ch * 8);
            } else {                        // B: 64 rows x 8 ch
                int u = idx - 1024;
                int row = u >> 3, ch = u & 7;
                CP16(st + 16384 + swz(row, ch),
                     B + (size_t)row * K_DIM + c * 64 + ch * 8);
            }
        }
    };

    fill(0, 0); CP_COMMIT();
    fill(1, 1); CP_COMMIT();
    fill(2, 2); CP_COMMIT();

    for (int c = 0; c < SH_CHUNKS; c++) {
        CP_WAIT2();
        __syncthreads();
        if (c + 3 < SH_CHUNKS) fill((c + 3) & 3, c + 3);
        CP_COMMIT();
        uint32_t st = sb + (c & 3) * SH_STAGE;
        #pragma unroll
        for (int ks = 0; ks < 4; ks++) {
            uint32_t aa[2][4], bb[2][4];
            #pragma unroll
            for (int mt = 0; mt < 2; mt++) {
                int row = m_off + mt * 16 + (lane & 15);
                int ch = ks * 2 + (lane >> 4);
                LDSM4(aa[mt], st + swz(row, ch));
            }
            #pragma unroll
            for (int p = 0; p < 2; p++) {
                int row = n_off + p * 16 + (lane & 15);
                int ch = ks * 2 + (lane >> 4);
                LDSM4(bb[p], st + 16384 + swz(row, ch));
            }
            #pragma unroll
            for (int mt = 0; mt < 2; mt++)
                #pragma unroll
                for (int p = 0; p < 2; p++) {
                    MMA_F16(acc[mt][2 * p],     aa[mt], bb[p][0], bb[p][2]);
                    MMA_F16(acc[mt][2 * p + 1], aa[mt], bb[p][1], bb[p][3]);
                }
        }
    }

    #pragma unroll
    for (int mt = 0; mt < 2; mt++)
        #pragma unroll
        for (int j = 0; j < 4; j++) {
            int row = row0 + m_off + mt * 16 + (lane >> 2);
            int col = n_off + j * 8 + ((lane & 3) << 1);
            *reinterpret_cast<__half2*>(g_sh16 + (size_t)row * R_DIM + col)
                = __floats2half2_rn(acc[mt][j][0], acc[mt][j][1]);
            *reinterpret_cast<__half2*>(g_sh16 + (size_t)(row + 8) * R_DIM + col)
                = __floats2half2_rn(acc[mt][j][2], acc[mt][j][3]);
        }
}

// =============================================================================
// Main GEMM: out[8192,4096] = x @ W^T (+ fused LoRA expand over rank 64).
// CTA tile 128x256, 512 threads (16 warps: 4m x 4n, warp tile 32x64), BK=64.
// R9: A-fragment double-buffer across ks, B LDSM interleaved with MMAs,
// fill prefetch issued before compute. Stage 48KB x 4 = 192KB.
// =============================================================================
#define MN_STAGE 49152
#define MN_CHUNKS (K_DIM / 64 + 1)   // 65

__global__ __launch_bounds__(512, 1) void gemm_main(
    const int* __restrict__ gl, int n_groups, float* __restrict__ out)
{
    extern __shared__ char smem[];
    uint32_t sb = smem_u32(smem);
    int tid = threadIdx.x, lane = tid & 31, w = tid >> 5;
    int m_off = (w & 3) * 32, n_off = (w >> 2) * 64;
    int row0 = blockIdx.y * 128;
    int col0 = blockIdx.x * 256;
    int g = find_group(gl, n_groups, row0);

    float acc[2][8][4];
    #pragma unroll
    for (int i = 0; i < 2; i++)
        #pragma unroll
        for (int j = 0; j < 8; j++)
            #pragma unroll
            for (int q = 0; q < 4; q++) acc[i][j][q] = 0.f;

    auto fill = [&](int s, int c) {
        uint32_t st = sb + s * MN_STAGE;
        const __half *pA, *pB;
        size_t lda, ldb;
        if (c < K_DIM / 64) {
            pA = g_x16 + (size_t)row0 * K_DIM + c * 64;
            pB = g_w16 + (size_t)col0 * K_DIM + c * 64;
            lda = K_DIM; ldb = K_DIM;
        } else {
            pA = g_sh16 + (size_t)row0 * R_DIM;
            pB = g_lb16 + ((size_t)g * N_DIM + col0) * R_DIM;
            lda = R_DIM; ldb = R_DIM;
        }
        #pragma unroll
        for (int it = 0; it < 6; it++) {
            int idx = tid + it * 512;
            if (idx < 1024) {               // A: 128 rows x 8 ch
                int row = idx >> 3, ch = idx & 7;
                CP16(st + swz(row, ch), pA + (size_t)row * lda + ch * 8);
            } else {                        // B: 256 rows x 8 ch
                int u = idx - 1024;
                int row = u >> 3, ch = u & 7;
                CP16(st + 16384 + swz(row, ch), pB + (size_t)row * ldb + ch * 8);
            }
        }
    };

    fill(0, 0); CP_COMMIT();
    fill(1, 1); CP_COMMIT();
    fill(2, 2); CP_COMMIT();

    const int a_r = lane & 15;          // A ldmatrix row-in-16
    const int a_c = lane >> 4;          // A ldmatrix ch parity
    for (int c = 0; c < MN_CHUNKS; c++) {
        CP_WAIT2();
        __syncthreads();
        // prefetch chunk c+3 FIRST: full compute window of cp.async lead time.
        // stage (c+3)&3 == (c-1)&3; its readers finished before the barrier.
        if (c + 3 < MN_CHUNKS) fill((c + 3) & 3, c + 3);
        CP_COMMIT();

        uint32_t st = sb + (c & 3) * MN_STAGE;
        uint32_t aa[2][2][4];           // [ks-parity buffer][mt][frag]
        #pragma unroll
        for (int mt = 0; mt < 2; mt++)
            LDSM4(aa[0][mt], st + swz(m_off + mt * 16 + a_r, a_c));

        #pragma unroll
        for (int ks = 0; ks < 4; ks++) {
            int cur = ks & 1;
            // prefetch next ks's A fragments under this ks's MMAs
            if (ks < 3) {
                #pragma unroll
                for (int mt = 0; mt < 2; mt++)
                    LDSM4(aa[cur ^ 1][mt],
                          st + swz(m_off + mt * 16 + a_r, (ks + 1) * 2 + a_c));
            }
            #pragma unroll
            for (int p = 0; p < 4; p++) {
                uint32_t bb[4];
                int row = n_off + p * 16 + (lane & 15);
                int ch = ks * 2 + (lane >> 4);
                LDSM4(bb, st + 16384 + swz(row, ch));
                MMA_F16(acc[0][2 * p],     aa[cur][0], bb[0], bb[2]);
                MMA_F16(acc[0][2 * p + 1], aa[cur][0], bb[1], bb[3]);
                MMA_F16(acc[1][2 * p],     aa[cur][1], bb[0], bb[2]);
                MMA_F16(acc[1][2 * p + 1], aa[cur][1], bb[1], bb[3]);
            }
        }
    }

    #pragma unroll
    for (int mt = 0; mt < 2; mt++)
        #pragma unroll
        for (int j = 0; j < 8; j++) {
            int row = row0 + m_off + mt * 16 + (lane >> 2);
            int col = col0 + n_off + j * 8 + ((lane & 3) << 1);
            *reinterpret_cast<float2*>(out + (size_t)row * N_DIM + col)
                = make_float2(acc[mt][j][0], acc[mt][j][1]);
            *reinterpret_cast<float2*>(out + (size_t)(row + 8) * N_DIM + col)
                = make_float2(acc[mt][j][2], acc[mt][j][3]);
        }
}

// ---------------- launch -----------------------------------------------------
extern "C" void kernel_launch(void* const* d_in, const int* in_sizes, int n_in,
                              void* d_out, int out_size) {
    const float* x      = (const float*)d_in[0];
    const float* W      = (const float*)d_in[1];
    const float* lora_a = (const float*)d_in[2];
    const float* lora_b = (const float*)d_in[3];
    const int*   gl     = (const int*)d_in[4];
    const int n_groups  = in_sizes[4];
    float* out = (float*)d_out;

    cudaFuncSetAttribute(shrink_gemm, cudaFuncAttributeMaxDynamicSharedMemorySize,
                         4 * SH_STAGE);
    cudaFuncSetAttribute(gemm_main, cudaFuncAttributeMaxDynamicSharedMemorySize,
                         4 * MN_STAGE);

    cvt_x_kernel<<<(T_DIM * (size_t)K_DIM / 4) / 256, 256>>>(x);
    cvt_w_kernel<<<(N_DIM * (size_t)K_DIM / 4) / 256, 256>>>(W);
    cvt_la_kernel<<<((size_t)NGRP * R_DIM * K_DIM / 4) / 256, 256>>>(lora_a);
    lorab_t_kernel<<<dim3(N_DIM / 64, NGRP), 256>>>(lora_b);

    shrink_gemm<<<T_DIM / 128, 256, 4 * SH_STAGE>>>(gl, n_groups);
    gemm_main<<<dim3(N_DIM / 256, T_DIM / 128), 512, 4 * MN_STAGE>>>(
        gl, n_groups, out);
}

// round 10
// speedup vs baseline: 1.1454x; 1.1454x over previous
#include <cuda_runtime.h>
#include <cuda_fp16.h>
#include <cstdint>

#define T_DIM 8192
#define K_DIM 4096
#define N_DIM 4096
#define R_DIM 64
#define NGRP  8

// ---------------- static device scratch (alloc forbidden) -------------------
__device__ __half g_x16[(size_t)T_DIM * K_DIM];
__device__ __half g_w16[(size_t)N_DIM * K_DIM];
__device__ __half g_la16[(size_t)NGRP * R_DIM * K_DIM];
__device__ __half g_lb16[(size_t)NGRP * N_DIM * R_DIM];   // [g][n][r] transposed
__device__ __half g_sh16[(size_t)T_DIM * R_DIM];

// ---------------- asm helpers (base ISA only: sm_80-class) ------------------
__device__ __forceinline__ uint32_t smem_u32(const void* p) {
    uint32_t a;
    asm("{ .reg .u64 t; cvta.to.shared.u64 t, %1; cvt.u32.u64 %0, t; }"
        : "=r"(a) : "l"(p));
    return a;
}
#define CP16(dst, src) \
    asm volatile("cp.async.cg.shared.global [%0], [%1], 16;" :: "r"(dst), "l"(src))
#define CP_COMMIT() asm volatile("cp.async.commit_group;" ::: "memory")
#define CP_WAIT1()  asm volatile("cp.async.wait_group 1;"  ::: "memory")
#define CP_WAIT2()  asm volatile("cp.async.wait_group 2;"  ::: "memory")

#define LDSM4(d, addr) \
    asm volatile("ldmatrix.sync.aligned.m8n8.x4.shared.b16 {%0,%1,%2,%3}, [%4];" \
        : "=r"((d)[0]), "=r"((d)[1]), "=r"((d)[2]), "=r"((d)[3]) : "r"(addr))

#define MMA_F16(ac, a, b0, b1) \
    asm volatile("mma.sync.aligned.m16n8k16.row.col.f32.f16.f16.f32 " \
        "{%0,%1,%2,%3}, {%4,%5,%6,%7}, {%8,%9}, {%0,%1,%2,%3};" \
        : "+f"((ac)[0]), "+f"((ac)[1]), "+f"((ac)[2]), "+f"((ac)[3]) \
        : "r"((a)[0]), "r"((a)[1]), "r"((a)[2]), "r"((a)[3]), "r"(b0), "r"(b1))

// smem byte offset of 16B chunk (row, ch) within a tile of 128B rows (BK=64).
// Full 8-way XOR swizzle: ldmatrix (8 rows, same ch) hits 8 distinct 16B banks.
__device__ __forceinline__ uint32_t swz(int row, int ch) {
    return (uint32_t)((row << 7) | (((ch ^ (row & 7)) & 7) << 4));
}

__device__ __forceinline__ int find_group(const int* __restrict__ gl,
                                          int n_groups, int token) {
    int g = 0;
    while (g < n_groups - 1 && token >= gl[g]) g++;
    return g;
}

// ---------------- pre-pass kernels ------------------------------------------
// Fused fp32->fp16 conversion of x, W, lora_a in ONE kernel (also shifts
// gemm_main into ncu's sampled launch slot).
#define NX4 ((size_t)T_DIM * K_DIM / 4)
#define NW4 ((size_t)N_DIM * K_DIM / 4)
#define NL4 ((size_t)NGRP * R_DIM * K_DIM / 4)

__global__ __launch_bounds__(256) void cvt_all_kernel(
    const float* __restrict__ x, const float* __restrict__ W,
    const float* __restrict__ la)
{
    size_t i = (size_t)blockIdx.x * 256 + threadIdx.x;
    const float* src;
    __half2* dst;
    size_t j;
    if (i < NX4) {
        src = x; dst = reinterpret_cast<__half2*>(g_x16); j = i;
    } else if (i < NX4 + NW4) {
        src = W; dst = reinterpret_cast<__half2*>(g_w16); j = i - NX4;
    } else {
        src = la; dst = reinterpret_cast<__half2*>(g_la16); j = i - NX4 - NW4;
    }
    float4 v = reinterpret_cast<const float4*>(src)[j];
    dst[2 * j]     = __floats2half2_rn(v.x, v.y);
    dst[2 * j + 1] = __floats2half2_rn(v.z, v.w);
}

// transpose lora_b[g][r][n] -> [g][n][r] fp16
__global__ __launch_bounds__(256) void lorab_t_kernel(const float* __restrict__ lb) {
    __shared__ float t[64][65];
    int g = blockIdx.y;
    int n0 = blockIdx.x * 64;
    for (int idx = threadIdx.x; idx < 4096; idx += 256) {
        int r = idx >> 6, n = idx & 63;
        t[n][r] = lb[((size_t)g * R_DIM + r) * N_DIM + n0 + n];
    }
    __syncthreads();
    for (int idx = threadIdx.x; idx < 4096; idx += 256) {
        int n = idx >> 6, r = idx & 63;
        g_lb16[((size_t)g * N_DIM + n0 + n) * R_DIM + r] = __float2half_rn(t[n][r]);
    }
}

// =============================================================================
// Shrink GEMM: shrink[8192,64] = x @ lora_a[g]^T, single fp16 term.
// CTA tile 128x64, 256 threads (8 warps: 4m x 2n, warp tile 32x32), BK=64.
// =============================================================================
#define SH_STAGE 24576
#define SH_CHUNKS (K_DIM / 64)   // 64

__global__ __launch_bounds__(256, 1) void shrink_gemm(
    const int* __restrict__ gl, int n_groups)
{
    extern __shared__ char smem[];
    uint32_t sb = smem_u32(smem);
    int tid = threadIdx.x, lane = tid & 31, w = tid >> 5;
    int m_off = (w & 3) * 32, n_off = (w >> 2) * 32;
    int row0 = blockIdx.x * 128;
    int g = find_group(gl, n_groups, row0);

    const __half* A = g_x16 + (size_t)row0 * K_DIM;
    const __half* B = g_la16 + (size_t)g * R_DIM * K_DIM;

    float acc[2][4][4];
    #pragma unroll
    for (int i = 0; i < 2; i++)
        #pragma unroll
        for (int j = 0; j < 4; j++)
            #pragma unroll
            for (int q = 0; q < 4; q++) acc[i][j][q] = 0.f;

    auto fill = [&](int s, int c) {
        uint32_t st = sb + s * SH_STAGE;
        #pragma unroll
        for (int it = 0; it < 6; it++) {
            int idx = tid + it * 256;
            if (idx < 1024) {               // A: 128 rows x 8 ch
                int row = idx >> 3, ch = idx & 7;
                CP16(st + swz(row, ch),
                     A + (size_t)row * K_DIM + c * 64 + ch * 8);
            } else {                        // B: 64 rows x 8 ch
                int u = idx - 1024;
                int row = u >> 3, ch = u & 7;
                CP16(st + 16384 + swz(row, ch),
                     B + (size_t)row * K_DIM + c * 64 + ch * 8);
            }
        }
    };

    fill(0, 0); CP_COMMIT();
    fill(1, 1); CP_COMMIT();
    fill(2, 2); CP_COMMIT();

    for (int c = 0; c < SH_CHUNKS; c++) {
        CP_WAIT2();
        __syncthreads();
        uint32_t st = sb + (c & 3) * SH_STAGE;
        #pragma unroll
        for (int ks = 0; ks < 4; ks++) {
            uint32_t aa[2][4], bb[2][4];
            #pragma unroll
            for (int mt = 0; mt < 2; mt++) {
                int row = m_off + mt * 16 + (lane & 15);
                int ch = ks * 2 + (lane >> 4);
                LDSM4(aa[mt], st + swz(row, ch));
            }
            #pragma unroll
            for (int p = 0; p < 2; p++) {
                int row = n_off + p * 16 + (lane & 15);
                int ch = ks * 2 + (lane >> 4);
                LDSM4(bb[p], st + 16384 + swz(row, ch));
            }
            #pragma unroll
            for (int mt = 0; mt < 2; mt++)
                #pragma unroll
                for (int p = 0; p < 2; p++) {
                    MMA_F16(acc[mt][2 * p],     aa[mt], bb[p][0], bb[p][2]);
                    MMA_F16(acc[mt][2 * p + 1], aa[mt], bb[p][1], bb[p][3]);
                }
        }
        if (c + 3 < SH_CHUNKS) fill((c + 3) & 3, c + 3);
        CP_COMMIT();
    }

    #pragma unroll
    for (int mt = 0; mt < 2; mt++)
        #pragma unroll
        for (int j = 0; j < 4; j++) {
            int row = row0 + m_off + mt * 16 + (lane >> 2);
            int col = n_off + j * 8 + ((lane & 3) << 1);
            *reinterpret_cast<__half2*>(g_sh16 + (size_t)row * R_DIM + col)
                = __floats2half2_rn(acc[mt][j][0], acc[mt][j][1]);
            *reinterpret_cast<__half2*>(g_sh16 + (size_t)(row + 8) * R_DIM + col)
                = __floats2half2_rn(acc[mt][j][2], acc[mt][j][3]);
        }
}

// =============================================================================
// Main GEMM: out[8192,4096] = x @ W^T (+ fused LoRA expand over rank 64).
// R10: CTA tile 128x128, 256 threads (8 warps: 4m x 2n, warp tile 32x64 —
// identical per-warp fragment/MMA pattern to the 870us R7 kernel), BK=64,
// 3 stages x 32KB = 96KB -> 2 CTAs/SM for cross-CTA latency hiding.
// Chunks: 64 base-K + 1 LoRA (rank 64).
// =============================================================================
#define MN_STAGE 32768
#define MN_CHUNKS (K_DIM / 64 + 1)   // 65

__global__ __launch_bounds__(256, 2) void gemm_main(
    const int* __restrict__ gl, int n_groups, float* __restrict__ out)
{
    extern __shared__ char smem[];
    uint32_t sb = smem_u32(smem);
    int tid = threadIdx.x, lane = tid & 31, w = tid >> 5;
    int m_off = (w & 3) * 32, n_off = (w >> 2) * 64;
    int row0 = blockIdx.y * 128;
    int col0 = blockIdx.x * 128;
    int g = find_group(gl, n_groups, row0);

    float acc[2][8][4];
    #pragma unroll
    for (int i = 0; i < 2; i++)
        #pragma unroll
        for (int j = 0; j < 8; j++)
            #pragma unroll
            for (int q = 0; q < 4; q++) acc[i][j][q] = 0.f;

    auto fill = [&](int s, int c) {
        uint32_t st = sb + s * MN_STAGE;
        const __half *pA, *pB;
        size_t lda, ldb;
        if (c < K_DIM / 64) {
            pA = g_x16 + (size_t)row0 * K_DIM + c * 64;
            pB = g_w16 + (size_t)col0 * K_DIM + c * 64;
            lda = K_DIM; ldb = K_DIM;
        } else {
            pA = g_sh16 + (size_t)row0 * R_DIM;
            pB = g_lb16 + ((size_t)g * N_DIM + col0) * R_DIM;
            lda = R_DIM; ldb = R_DIM;
        }
        #pragma unroll
        for (int it = 0; it < 8; it++) {
            int idx = tid + it * 256;
            if (idx < 1024) {               // A: 128 rows x 8 ch
                int row = idx >> 3, ch = idx & 7;
                CP16(st + swz(row, ch), pA + (size_t)row * lda + ch * 8);
            } else {                        // B: 128 rows x 8 ch
                int u = idx - 1024;
                int row = u >> 3, ch = u & 7;
                CP16(st + 16384 + swz(row, ch), pB + (size_t)row * ldb + ch * 8);
            }
        }
    };

    fill(0, 0); CP_COMMIT();
    fill(1, 1); CP_COMMIT();

    for (int c = 0; c < MN_CHUNKS; c++) {
        CP_WAIT1();
        __syncthreads();
        uint32_t st = sb + (c % 3) * MN_STAGE;
        #pragma unroll
        for (int ks = 0; ks < 4; ks++) {
            uint32_t aa[2][4], bb[4][4];
            #pragma unroll
            for (int mt = 0; mt < 2; mt++) {
                int row = m_off + mt * 16 + (lane & 15);
                int ch = ks * 2 + (lane >> 4);
                LDSM4(aa[mt], st + swz(row, ch));
            }
            #pragma unroll
            for (int p = 0; p < 4; p++) {
                int row = n_off + p * 16 + (lane & 15);
                int ch = ks * 2 + (lane >> 4);
                LDSM4(bb[p], st + 16384 + swz(row, ch));
            }
            #pragma unroll
            for (int mt = 0; mt < 2; mt++)
                #pragma unroll
                for (int p = 0; p < 4; p++) {
                    MMA_F16(acc[mt][2 * p],     aa[mt], bb[p][0], bb[p][2]);
                    MMA_F16(acc[mt][2 * p + 1], aa[mt], bb[p][1], bb[p][3]);
                }
        }
        if (c + 2 < MN_CHUNKS) fill((c + 2) % 3, c + 2);
        CP_COMMIT();
    }

    #pragma unroll
    for (int mt = 0; mt < 2; mt++)
        #pragma unroll
        for (int j = 0; j < 8; j++) {
            int row = row0 + m_off + mt * 16 + (lane >> 2);
            int col = col0 + n_off + j * 8 + ((lane & 3) << 1);
            *reinterpret_cast<float2*>(out + (size_t)row * N_DIM + col)
                = make_float2(acc[mt][j][0], acc[mt][j][1]);
            *reinterpret_cast<float2*>(out + (size_t)(row + 8) * N_DIM + col)
                = make_float2(acc[mt][j][2], acc[mt][j][3]);
        }
}

// ---------------- launch -----------------------------------------------------
extern "C" void kernel_launch(void* const* d_in, const int* in_sizes, int n_in,
                              void* d_out, int out_size) {
    const float* x      = (const float*)d_in[0];
    const float* W      = (const float*)d_in[1];
    const float* lora_a = (const float*)d_in[2];
    const float* lora_b = (const float*)d_in[3];
    const int*   gl     = (const int*)d_in[4];
    const int n_groups  = in_sizes[4];
    float* out = (float*)d_out;

    cudaFuncSetAttribute(shrink_gemm, cudaFuncAttributeMaxDynamicSharedMemorySize,
                         4 * SH_STAGE);
    cudaFuncSetAttribute(gemm_main, cudaFuncAttributeMaxDynamicSharedMemorySize,
                         3 * MN_STAGE);

    // launch order: cvt_all(0), lorab(1), shrink(2), gemm_main(3)
    cvt_all_kernel<<<(unsigned)((NX4 + NW4 + NL4) / 256), 256>>>(x, W, lora_a);
    lorab_t_kernel<<<dim3(N_DIM / 64, NGRP), 256>>>(lora_b);
    shrink_gemm<<<T_DIM / 128, 256, 4 * SH_STAGE>>>(gl, n_groups);
    gemm_main<<<dim3(N_DIM / 128, T_DIM / 128), 256, 3 * MN_STAGE>>>(
        gl, n_groups, out);
}